// round 3
// baseline (speedup 1.0000x reference)
#include <cuda_runtime.h>
#include <cuda_bf16.h>
#include <math.h>

// ---------------------------------------------------------------------------
// HardNegativeContrastiveLoss, N=8192, D=256, temperature 0.07, top-k 32.
//
// Fused design (no NxN scratch):
//   pass_kernel: grid(128, 2). blockIdx.y selects direction:
//     dir 0: X=image, Y=current  (i2c rows)
//     dir 1: X=current, Y=image  (c2i rows == columns of logits)
//   Each CTA owns BM=64 rows, sweeps all 64 column tiles of BN=128,
//   computes the 64x128 logits tile (fp32 FFMA2), scales by 1/T, masks the
//   diagonal, captures pos (diag), and updates per-row top-32 kept in warp
//   registers (1 entry/lane) with a broadcast threshold.
//   End of sweep: per-row loss = logsumexp([pos, top32]) - pos -> g_losses.
//   reduce_kernel: sums 16384 row losses, out = sum / 16384  (== (mi2c+mc2i)/2).
// ---------------------------------------------------------------------------

#define N_ROWS 8192
#define DIM    256
#define INV_T  (1.0f / 0.07f)
#define BM     64
#define BN     128
#define BK     16
#define NTHREADS 256
#define ROWS_PER_WARP 8   // BM / 8 warps

__device__ float g_losses[2 * N_ROWS];

typedef unsigned long long u64;

__device__ __forceinline__ u64 pack2(float lo, float hi) {
    u64 r;
    asm("mov.b64 %0, {%1, %2};" : "=l"(r) : "f"(lo), "f"(hi));
    return r;
}
__device__ __forceinline__ void unpack2(u64 v, float& lo, float& hi) {
    asm("mov.b64 {%0, %1}, %2;" : "=f"(lo), "=f"(hi) : "l"(v));
}
// Packed fp32x2 FMA (Blackwell): d = a*b + c elementwise on two fp32 lanes.
__device__ __forceinline__ u64 ffma2(u64 a, u64 b, u64 c) {
    u64 d;
    asm("fma.rn.f32x2 %0, %1, %2, %3;" : "=l"(d) : "l"(a), "l"(b), "l"(c));
    return d;
}

union SmemU {
    struct {
        float Xs[BK][BM];   // K-major transposed X tile (4 KB)
        float Ys[BK][BN];   // K-major transposed Y tile (8 KB)
    } g;
    float tile[BM][BN];     // staged logits tile for top-k (32 KB)
};

__global__ void __launch_bounds__(NTHREADS)
pass_kernel(const float* __restrict__ img, const float* __restrict__ cur) {
    const int dir  = blockIdx.y;
    const float* __restrict__ X = dir ? cur : img;
    const float* __restrict__ Y = dir ? img : cur;
    const int row0 = blockIdx.x * BM;

    const int tid   = threadIdx.x;
    const int lane  = tid & 31;
    const int warp  = tid >> 5;
    const int row_t = tid >> 4;   // 0..15, owns rows row_t*4 .. +3
    const int col_t = tid & 15;   // 0..15, owns cols col_t*8 .. +7

    __shared__ SmemU sm;
    __shared__ float pos_s[BM];

    // per-warp top-32 state: lane l holds list entry l of each of this warp's
    // 8 rows (rows warp*8 .. warp*8+7)
    float lv[ROWS_PER_WARP];
    float thr[ROWS_PER_WARP];
#pragma unroll
    for (int i = 0; i < ROWS_PER_WARP; i++) { lv[i] = -INFINITY; thr[i] = -INFINITY; }

    const int ldr = tid >> 2;          // 0..63
    const int k4  = (tid & 3) << 2;    // 0,4,8,12

    for (int nb = 0; nb < N_ROWS / BN; nb++) {
        u64 acc[4][4];
#pragma unroll
        for (int i = 0; i < 4; i++)
#pragma unroll
            for (int j = 0; j < 4; j++) acc[i][j] = 0ull;

        for (int kk = 0; kk < DIM; kk += BK) {
            // load X tile (64x16) and Y tile (128x16), store k-major
            float4 xv = *(const float4*)(X + (size_t)(row0 + ldr) * DIM + kk + k4);
            float4 y0 = *(const float4*)(Y + (size_t)(nb * BN + ldr) * DIM + kk + k4);
            float4 y1 = *(const float4*)(Y + (size_t)(nb * BN + ldr + 64) * DIM + kk + k4);
            sm.g.Xs[k4 + 0][ldr] = xv.x; sm.g.Xs[k4 + 1][ldr] = xv.y;
            sm.g.Xs[k4 + 2][ldr] = xv.z; sm.g.Xs[k4 + 3][ldr] = xv.w;
            sm.g.Ys[k4 + 0][ldr] = y0.x; sm.g.Ys[k4 + 1][ldr] = y0.y;
            sm.g.Ys[k4 + 2][ldr] = y0.z; sm.g.Ys[k4 + 3][ldr] = y0.w;
            sm.g.Ys[k4 + 0][ldr + 64] = y1.x; sm.g.Ys[k4 + 1][ldr + 64] = y1.y;
            sm.g.Ys[k4 + 2][ldr + 64] = y1.z; sm.g.Ys[k4 + 3][ldr + 64] = y1.w;
            __syncthreads();

#pragma unroll
            for (int k = 0; k < BK; k++) {
                float4 av = *(const float4*)&sm.g.Xs[k][row_t * 4];
                ulonglong2 bv0 = *(const ulonglong2*)&sm.g.Ys[k][col_t * 8];
                ulonglong2 bv1 = *(const ulonglong2*)&sm.g.Ys[k][col_t * 8 + 4];
                u64 b[4] = { bv0.x, bv0.y, bv1.x, bv1.y };
                float a[4] = { av.x, av.y, av.z, av.w };
#pragma unroll
                for (int i = 0; i < 4; i++) {
                    u64 aa = pack2(a[i], a[i]);
#pragma unroll
                    for (int j = 0; j < 4; j++)
                        acc[i][j] = ffma2(aa, b[j], acc[i][j]);
                }
            }
            __syncthreads();
        }

        // stage tile to smem: scale, mask diagonal, capture pos
#pragma unroll
        for (int i = 0; i < 4; i++) {
            const int r = row_t * 4 + i;
            const int grow = row0 + r;
#pragma unroll
            for (int j = 0; j < 4; j++) {
                float lo, hi;
                unpack2(acc[i][j], lo, hi);
                lo *= INV_T; hi *= INV_T;
                const int c0 = col_t * 8 + 2 * j;
                const int gcol = nb * BN + c0;
                if (gcol == grow)     { pos_s[r] = lo; lo = -INFINITY; }
                if (gcol + 1 == grow) { pos_s[r] = hi; hi = -INFINITY; }
                sm.tile[r][c0]     = lo;
                sm.tile[r][c0 + 1] = hi;
            }
        }
        __syncthreads();

        // top-k update: warp w handles rows w*8 .. w*8+7
#pragma unroll
        for (int rr = 0; rr < ROWS_PER_WARP; rr++) {
            const int r = warp * ROWS_PER_WARP + rr;
            float t = thr[rr];
#pragma unroll
            for (int q = 0; q < 4; q++) {
                float v = sm.tile[r][lane + 32 * q];
                unsigned mask = __ballot_sync(0xffffffffu, v > t);
                while (mask) {
                    const int src = __ffs(mask) - 1;
                    mask &= mask - 1;
                    float vv = __shfl_sync(0xffffffffu, v, src);
                    if (!(vv > t)) continue;
                    // replace the current min entry of this row's list with vv
                    float m = lv[rr]; int ml = lane;
#pragma unroll
                    for (int off = 16; off > 0; off >>= 1) {
                        float om = __shfl_xor_sync(0xffffffffu, m, off);
                        int   ol = __shfl_xor_sync(0xffffffffu, ml, off);
                        if (om < m || (om == m && ol < ml)) { m = om; ml = ol; }
                    }
                    if (lane == ml) lv[rr] = vv;
                    float t2 = lv[rr];
#pragma unroll
                    for (int off = 16; off > 0; off >>= 1)
                        t2 = fminf(t2, __shfl_xor_sync(0xffffffffu, t2, off));
                    t = t2;
                }
            }
            thr[rr] = t;
        }
        __syncthreads();
    }

    // per-row loss: logsumexp([pos, top32]) - pos
#pragma unroll
    for (int rr = 0; rr < ROWS_PER_WARP; rr++) {
        const int r = warp * ROWS_PER_WARP + rr;
        const float p = pos_s[r];
        float x = lv[rr];
        float m = x;
#pragma unroll
        for (int off = 16; off > 0; off >>= 1)
            m = fmaxf(m, __shfl_xor_sync(0xffffffffu, m, off));
        const float mm = fmaxf(m, p);
        float e = expf(x - mm);
#pragma unroll
        for (int off = 16; off > 0; off >>= 1)
            e += __shfl_xor_sync(0xffffffffu, e, off);
        const float s = e + expf(p - mm);
        if (lane == 0)
            g_losses[dir * N_ROWS + row0 + r] = mm + logf(s) - p;
    }
}

__global__ void reduce_kernel(float* __restrict__ out) {
    __shared__ double red[256];
    double s = 0.0;
    for (int i = threadIdx.x; i < 2 * N_ROWS; i += 256)
        s += (double)g_losses[i];
    red[threadIdx.x] = s;
    __syncthreads();
    for (int off = 128; off > 0; off >>= 1) {
        if (threadIdx.x < off) red[threadIdx.x] += red[threadIdx.x + off];
        __syncthreads();
    }
    if (threadIdx.x == 0)
        out[0] = (float)(red[0] / (double)(2 * N_ROWS));
}

extern "C" void kernel_launch(void* const* d_in, const int* in_sizes, int n_in,
                              void* d_out, int out_size) {
    const float* img = (const float*)d_in[0];
    const float* cur = (const float*)d_in[1];
    float* out = (float*)d_out;
    (void)in_sizes; (void)n_in; (void)out_size;

    dim3 grid(N_ROWS / BM, 2);
    pass_kernel<<<grid, NTHREADS>>>(img, cur);
    reduce_kernel<<<1, 256>>>(out);
}

// round 5
// speedup vs baseline: 3.0167x; 3.0167x over previous
#include <cuda_runtime.h>
#include <cuda_bf16.h>
#include <math.h>
#include <stdint.h>

// ---------------------------------------------------------------------------
// HardNegativeContrastiveLoss N=8192 D=256 T=0.07 top-k=32.
// mma.sync (HMMA) bf16 3-term error-split GEMM, fused top-32 + logsumexp.
// (tcgen05 PTX rejected: harness compiles PTX at .target sm_103, no 'a'.)
//
//  split_kernel : fp32 -> (bf16 hi, bf16 lo) both inputs
//  pass_kernel  : grid(64,2), 256 thr. CTA owns 128 rows, K=768 virtual
//                 (hi*hi + hi*lo + lo*hi), sweeps 64 col tiles of 128.
//                 A (hi+lo) resident in smem (128KB); B cp.async 3-buf pipe;
//                 ldmatrix + mma.m16n8k16; epilogue stages acc to smem,
//                 per-thread sorted top-32 in registers (half-row each).
//  reduce_kernel: mean of 16384 row losses.
// ---------------------------------------------------------------------------

#define N_ROWS 8192
#define DIM    256
#define INV_T  (1.0f / 0.07f)
#define BM     128
#define BN     128
#define NTHREADS 256
#define TILE_BYTES 16384        // 128 rows x 64 bf16 (128B/row), SW128
#define NCHUNK 12               // K=768 in chunks of 64
#define NB     (N_ROWS / BN)    // 64
#define NSTEP  (NB * NCHUNK)    // 768
#define OFF_A  0
#define OFF_B  (8 * TILE_BYTES)             // 131072
#define DYN_SMEM (OFF_B + 3 * TILE_BYTES + 1024)  // 181248 + align slack
#define STG_LD 66               // staging row stride (floats), anti-conflict

__device__ __nv_bfloat16 g_img_hi[N_ROWS * DIM];
__device__ __nv_bfloat16 g_img_lo[N_ROWS * DIM];
__device__ __nv_bfloat16 g_cur_hi[N_ROWS * DIM];
__device__ __nv_bfloat16 g_cur_lo[N_ROWS * DIM];
__device__ float g_losses[2 * N_ROWS];

#define SW(o) ((o) ^ (((o) >> 3) & 0x70))

__device__ __forceinline__ uint32_t smem_to_u32(const void* p) {
    uint32_t a;
    asm("{ .reg .u64 t; cvta.to.shared.u64 t, %1; cvt.u32.u64 %0, t; }"
        : "=r"(a) : "l"(p));
    return a;
}
__device__ __forceinline__ void cpa16(uint32_t dst, const void* src) {
    asm volatile("cp.async.cg.shared.global [%0], [%1], 16;"
                 :: "r"(dst), "l"(src) : "memory");
}
#define CP_COMMIT() asm volatile("cp.async.commit_group;" ::: "memory")
#define CP_WAIT2()  asm volatile("cp.async.wait_group 2;" ::: "memory")

__device__ __forceinline__ void ldsm_x4(uint32_t* r, uint32_t addr) {
    asm volatile("ldmatrix.sync.aligned.m8n8.x4.shared.b16 {%0,%1,%2,%3}, [%4];"
                 : "=r"(r[0]), "=r"(r[1]), "=r"(r[2]), "=r"(r[3]) : "r"(addr));
}
__device__ __forceinline__ void mma16816(float* c, const uint32_t* a,
                                         const uint32_t* b) {
    asm volatile(
        "mma.sync.aligned.m16n8k16.row.col.f32.bf16.bf16.f32 "
        "{%0,%1,%2,%3}, {%4,%5,%6,%7}, {%8,%9}, {%0,%1,%2,%3};"
        : "+f"(c[0]), "+f"(c[1]), "+f"(c[2]), "+f"(c[3])
        : "r"(a[0]), "r"(a[1]), "r"(a[2]), "r"(a[3]), "r"(b[0]), "r"(b[1]));
}

// ---------------------------------------------------------------------------
__global__ void split_kernel(const float* __restrict__ img,
                             const float* __restrict__ cur) {
    int i = blockIdx.x * blockDim.x + threadIdx.x;
    if (i < N_ROWS * DIM) {
        float a = img[i];
        __nv_bfloat16 h = __float2bfloat16(a);
        g_img_hi[i] = h;
        g_img_lo[i] = __float2bfloat16(a - __bfloat162float(h));
        float b = cur[i];
        __nv_bfloat16 h2 = __float2bfloat16(b);
        g_cur_hi[i] = h2;
        g_cur_lo[i] = __float2bfloat16(b - __bfloat162float(h2));
    }
}

// ---------------------------------------------------------------------------
__global__ void __launch_bounds__(NTHREADS, 1)
pass_kernel() {
    extern __shared__ char dsm[];
    __shared__ float stg[128 * STG_LD];   // 33792 B staging / merge scratch

    const uint32_t base = (smem_to_u32(dsm) + 1023u) & ~1023u;
    const int tid    = threadIdx.x;
    const int lane   = tid & 31;
    const int wid    = tid >> 5;
    const int warp_m = wid >> 1;     // 0..3 : rows warp_m*32..+31
    const int warp_n = wid & 1;      // 0..1 : cols warp_n*64..+63
    const int dir    = blockIdx.y;
    const int row0   = blockIdx.x * BM;

    const __nv_bfloat16* Xhi = dir ? g_cur_hi : g_img_hi;
    const __nv_bfloat16* Xlo = dir ? g_cur_lo : g_img_lo;
    const __nv_bfloat16* Yhi = dir ? g_img_hi : g_cur_hi;
    const __nv_bfloat16* Ylo = dir ? g_img_lo : g_cur_lo;

    const int ldrow = tid >> 1;            // 0..127
    const int ldseg = (tid & 1) * 64;      // byte offset within 128B row

    // ---- A resident tiles: 0..3 = Xhi chunks, 4..7 = Xlo chunks ----------
#pragma unroll
    for (int c = 0; c < 4; c++) {
        const char* p = (const char*)(Xhi + (size_t)(row0 + ldrow) * DIM + c * 64) + ldseg;
        uint32_t t0 = base + OFF_A + c * TILE_BYTES;
        uint32_t o0 = (uint32_t)ldrow * 128u + ldseg;
#pragma unroll
        for (int q = 0; q < 4; q++) {
            uint32_t off = o0 + q * 16;
            cpa16(t0 + SW(off), p + q * 16);
        }
    }
#pragma unroll
    for (int c = 0; c < 4; c++) {
        const char* p = (const char*)(Xlo + (size_t)(row0 + ldrow) * DIM + c * 64) + ldseg;
        uint32_t t0 = base + OFF_A + (4 + c) * TILE_BYTES;
        uint32_t o0 = (uint32_t)ldrow * 128u + ldseg;
#pragma unroll
        for (int q = 0; q < 4; q++) {
            uint32_t off = o0 + q * 16;
            cpa16(t0 + SW(off), p + q * 16);
        }
    }

    // B chunk load: step s -> kc=s%12 (term=kc/4: B src hi,lo,hi), buf=s%3
    auto issue = [&](int s) {
        int kc2 = s % NCHUNK, nb2 = s / NCHUNK;
        const __nv_bfloat16* src;
        int ch;
        if (kc2 < 4)       { src = Yhi; ch = kc2; }
        else if (kc2 < 8)  { src = Ylo; ch = kc2 - 4; }
        else               { src = Yhi; ch = kc2 - 8; }
        uint32_t t0 = base + OFF_B + (uint32_t)(s % 3) * TILE_BYTES;
        const char* p = (const char*)(src + (size_t)(nb2 * BN + ldrow) * DIM + ch * 64) + ldseg;
        uint32_t o0 = (uint32_t)ldrow * 128u + ldseg;
#pragma unroll
        for (int q = 0; q < 4; q++) {
            uint32_t off = o0 + q * 16;
            cpa16(t0 + SW(off), p + q * 16);
        }
    };

    issue(0); CP_COMMIT();   // group0 = A tiles + B0
    issue(1); CP_COMMIT();   // group1 = B1

    // per-thread top-32 (sorted desc, [31]=min) over this thread's half-row
    float list[32];
#pragma unroll
    for (int t = 0; t < 32; t++) list[t] = -INFINITY;
    float pos = -INFINITY;
    const int myrow = tid >> 1;
    const int grow  = row0 + myrow;
    const int chalf = (tid & 1) * 32;

    float acc[2][8][4];

    for (int cs = 0; cs < NSTEP; cs++) {
        const int kc = cs % NCHUNK;
        const int nb = cs / NCHUNK;

        __syncthreads();                       // buf (cs+2)%3 free to overwrite
        if (cs + 2 < NSTEP) issue(cs + 2);
        CP_COMMIT();
        CP_WAIT2();                            // B(cs) landed (this thread)
        __syncthreads();                       // ... for all threads

        if (kc == 0) {
#pragma unroll
            for (int mi = 0; mi < 2; mi++)
#pragma unroll
                for (int nj = 0; nj < 8; nj++)
#pragma unroll
                    for (int e = 0; e < 4; e++) acc[mi][nj][e] = 0.0f;
        }

        const int ta = (kc < 4) ? kc : ((kc < 8) ? kc - 4 : 4 + (kc - 8));
        const uint32_t aT = base + OFF_A + ta * TILE_BYTES;
        const uint32_t bT = base + OFF_B + (uint32_t)(cs % 3) * TILE_BYTES;

#pragma unroll
        for (int ks = 0; ks < 4; ks++) {
            uint32_t af[2][4];
#pragma unroll
            for (int mi = 0; mi < 2; mi++) {
                uint32_t off = (uint32_t)(warp_m * 32 + mi * 16 + (lane & 15)) * 128u
                             + ks * 32 + ((lane >> 4) << 4);
                ldsm_x4(af[mi], aT + SW(off));
            }
            uint32_t bf[8][2];
#pragma unroll
            for (int n4 = 0; n4 < 4; n4++) {
                uint32_t off = (uint32_t)(warp_n * 64 + n4 * 16 + ((lane >> 4) & 1) * 8
                             + (lane & 7)) * 128u
                             + ks * 32 + (((lane >> 3) & 1) << 4);
                uint32_t r[4];
                ldsm_x4(r, bT + SW(off));
                bf[2 * n4][0] = r[0]; bf[2 * n4][1] = r[1];
                bf[2 * n4 + 1][0] = r[2]; bf[2 * n4 + 1][1] = r[3];
            }
#pragma unroll
            for (int mi = 0; mi < 2; mi++)
#pragma unroll
                for (int nj = 0; nj < 8; nj++)
                    mma16816(acc[mi][nj], af[mi], bf[nj]);
        }

        if (kc == NCHUNK - 1) {
            // ------- epilogue for tile nb: two 64-col halves through stg ----
#pragma unroll
            for (int h = 0; h < 2; h++) {
                __syncthreads();               // prior scan done, stg free
                if (warp_n == h) {
#pragma unroll
                    for (int mi = 0; mi < 2; mi++)
#pragma unroll
                        for (int nj = 0; nj < 8; nj++) {
                            int r_ = warp_m * 32 + mi * 16 + (lane >> 2);
                            int c_ = nj * 8 + (lane & 3) * 2;
                            *(float2*)&stg[r_ * STG_LD + c_] =
                                make_float2(acc[mi][nj][0], acc[mi][nj][1]);
                            *(float2*)&stg[(r_ + 8) * STG_LD + c_] =
                                make_float2(acc[mi][nj][2], acc[mi][nj][3]);
                        }
                }
                __syncthreads();
                const int cb = nb * BN + h * 64 + chalf;
#pragma unroll
                for (int j = 0; j < 32; j++) {
                    float v = stg[myrow * STG_LD + chalf + j] * INV_T;
                    if (cb + j == grow) { pos = v; v = -INFINITY; }
                    if (v > list[31]) {
                        float x = v;
#pragma unroll
                        for (int t2 = 0; t2 < 32; t2++) {
                            float a_  = list[t2];
                            float hi_ = fmaxf(a_, x);
                            x         = fminf(a_, x);
                            list[t2]  = hi_;
                        }
                    }
                }
            }
        }
    }

    // ---- merge the two half-row lists of each row, emit per-row loss ------
    __syncthreads();
    float* fl = stg;                     // 256 slots x 33 floats = 8448 <= stg
#pragma unroll
    for (int i = 0; i < 32; i++) fl[tid * 33 + i] = list[i];
    fl[tid * 33 + 32] = pos;
    __syncthreads();
    if (!(tid & 1)) {
        const float* A_ = &fl[tid * 33];
        const float* B_ = &fl[(tid + 1) * 33];
        float pm = fmaxf(A_[32], B_[32]);            // the real diagonal logit
        float m  = fmaxf(pm, fmaxf(A_[0], B_[0]));
        float s  = expf(pm - m);
        int ia = 0, ib = 0;
        for (int it = 0; it < 32; it++) {
            float va = (ia < 32) ? A_[ia] : -INFINITY;
            float vb = (ib < 32) ? B_[ib] : -INFINITY;
            if (va >= vb) { s += expf(va - m); ia++; }
            else          { s += expf(vb - m); ib++; }
        }
        g_losses[dir * N_ROWS + grow] = m + logf(s) - pm;
    }
}

// ---------------------------------------------------------------------------
__global__ void reduce_kernel(float* __restrict__ out) {
    __shared__ double red[256];
    double s = 0.0;
    for (int i = threadIdx.x; i < 2 * N_ROWS; i += 256)
        s += (double)g_losses[i];
    red[threadIdx.x] = s;
    __syncthreads();
    for (int off = 128; off > 0; off >>= 1) {
        if (threadIdx.x < off) red[threadIdx.x] += red[threadIdx.x + off];
        __syncthreads();
    }
    if (threadIdx.x == 0)
        out[0] = (float)(red[0] / (double)(2 * N_ROWS));
}

// ---------------------------------------------------------------------------
extern "C" void kernel_launch(void* const* d_in, const int* in_sizes, int n_in,
                              void* d_out, int out_size) {
    const float* img = (const float*)d_in[0];
    const float* cur = (const float*)d_in[1];
    float* out = (float*)d_out;
    (void)in_sizes; (void)n_in; (void)out_size;

    cudaFuncSetAttribute(pass_kernel,
                         cudaFuncAttributeMaxDynamicSharedMemorySize, DYN_SMEM);

    split_kernel<<<(N_ROWS * DIM + 255) / 256, 256>>>(img, cur);
    dim3 grid(NB, 2);
    pass_kernel<<<grid, NTHREADS, DYN_SMEM>>>();
    reduce_kernel<<<1, 256>>>(out);
}

// round 7
// speedup vs baseline: 4.4475x; 1.4743x over previous
#include <cuda_runtime.h>
#include <cuda_bf16.h>
#include <math.h>
#include <stdint.h>

// ---------------------------------------------------------------------------
// HardNegativeContrastiveLoss N=8192 D=256 T=0.07 top-k=32.
// mma.sync (HMMA) bf16 2-term error-split GEMM, fused top-32 + logsumexp.
//   x·y ≈ hi(x)·hi(y) + lo(x)·hi(y)   (exact in x; dropped x·lo(y) term has
//   per-logit sigma ~0.26 abs vs loss ~870 and 16384-row mean -> ~1e-5 rel)
// Both terms share the same B tile (hi(y)): B is loaded ONCE per K-chunk and
// its ldmatrix fragments feed both the A-hi and A-lo MMAs. 256 steps total.
// ---------------------------------------------------------------------------

#define N_ROWS 8192
#define DIM    256
#define INV_T  (1.0f / 0.07f)
#define BM     128
#define BN     128
#define NTHREADS 256
#define TILE_BYTES 16384        // 128 rows x 64 bf16 (128B/row), SW128
#define NCHUNK 4                // B chunks per tile (K=256 of hi(y))
#define NB     (N_ROWS / BN)    // 64
#define NSTEP  (NB * NCHUNK)    // 256
#define OFF_A  0
#define OFF_B  (8 * TILE_BYTES)             // 131072
#define DYN_SMEM (OFF_B + 3 * TILE_BYTES + 1024)
#define STG_LD 66               // staging row stride (floats), anti-conflict

__device__ __nv_bfloat16 g_img_hi[N_ROWS * DIM];
__device__ __nv_bfloat16 g_img_lo[N_ROWS * DIM];
__device__ __nv_bfloat16 g_cur_hi[N_ROWS * DIM];
__device__ __nv_bfloat16 g_cur_lo[N_ROWS * DIM];
__device__ float g_losses[2 * N_ROWS];

#define SW(o) ((o) ^ (((o) >> 3) & 0x70))

__device__ __forceinline__ uint32_t smem_to_u32(const void* p) {
    uint32_t a;
    asm("{ .reg .u64 t; cvta.to.shared.u64 t, %1; cvt.u32.u64 %0, t; }"
        : "=r"(a) : "l"(p));
    return a;
}
__device__ __forceinline__ void cpa16(uint32_t dst, const void* src) {
    asm volatile("cp.async.cg.shared.global [%0], [%1], 16;"
                 :: "r"(dst), "l"(src) : "memory");
}
#define CP_COMMIT() asm volatile("cp.async.commit_group;" ::: "memory")
#define CP_WAIT2()  asm volatile("cp.async.wait_group 2;" ::: "memory")

__device__ __forceinline__ void ldsm_x4(uint32_t* r, uint32_t addr) {
    asm volatile("ldmatrix.sync.aligned.m8n8.x4.shared.b16 {%0,%1,%2,%3}, [%4];"
                 : "=r"(r[0]), "=r"(r[1]), "=r"(r[2]), "=r"(r[3]) : "r"(addr));
}
__device__ __forceinline__ void mma16816(float* c, const uint32_t* a,
                                         const uint32_t* b) {
    asm volatile(
        "mma.sync.aligned.m16n8k16.row.col.f32.bf16.bf16.f32 "
        "{%0,%1,%2,%3}, {%4,%5,%6,%7}, {%8,%9}, {%0,%1,%2,%3};"
        : "+f"(c[0]), "+f"(c[1]), "+f"(c[2]), "+f"(c[3])
        : "r"(a[0]), "r"(a[1]), "r"(a[2]), "r"(a[3]), "r"(b[0]), "r"(b[1]));
}

// ---------------------------------------------------------------------------
__global__ void split_kernel(const float* __restrict__ img,
                             const float* __restrict__ cur) {
    int i = blockIdx.x * blockDim.x + threadIdx.x;
    if (i < N_ROWS * DIM) {
        float a = img[i];
        __nv_bfloat16 h = __float2bfloat16(a);
        g_img_hi[i] = h;
        g_img_lo[i] = __float2bfloat16(a - __bfloat162float(h));
        float b = cur[i];
        __nv_bfloat16 h2 = __float2bfloat16(b);
        g_cur_hi[i] = h2;
        g_cur_lo[i] = __float2bfloat16(b - __bfloat162float(h2));
    }
}

// ---------------------------------------------------------------------------
__global__ void __launch_bounds__(NTHREADS, 1)
pass_kernel() {
    extern __shared__ char dsm[];
    __shared__ float stg[128 * STG_LD];   // staging / merge scratch

    const uint32_t base = (smem_to_u32(dsm) + 1023u) & ~1023u;
    const int tid    = threadIdx.x;
    const int lane   = tid & 31;
    const int wid    = tid >> 5;
    const int warp_m = wid >> 1;     // 0..3 : rows warp_m*32..+31
    const int warp_n = wid & 1;      // 0..1 : cols warp_n*64..+63
    const int dir    = blockIdx.y;
    const int row0   = blockIdx.x * BM;

    const __nv_bfloat16* Xhi = dir ? g_cur_hi : g_img_hi;
    const __nv_bfloat16* Xlo = dir ? g_cur_lo : g_img_lo;
    const __nv_bfloat16* Yhi = dir ? g_img_hi : g_cur_hi;

    const int ldrow = tid >> 1;            // 0..127
    const int ldseg = (tid & 1) * 64;      // byte offset within 128B row

    // ---- A resident tiles: 0..3 = Xhi chunks, 4..7 = Xlo chunks ----------
#pragma unroll
    for (int c = 0; c < 4; c++) {
        const char* p = (const char*)(Xhi + (size_t)(row0 + ldrow) * DIM + c * 64) + ldseg;
        uint32_t t0 = base + OFF_A + c * TILE_BYTES;
        uint32_t o0 = (uint32_t)ldrow * 128u + ldseg;
#pragma unroll
        for (int q = 0; q < 4; q++) {
            uint32_t off = o0 + q * 16;
            cpa16(t0 + SW(off), p + q * 16);
        }
    }
#pragma unroll
    for (int c = 0; c < 4; c++) {
        const char* p = (const char*)(Xlo + (size_t)(row0 + ldrow) * DIM + c * 64) + ldseg;
        uint32_t t0 = base + OFF_A + (4 + c) * TILE_BYTES;
        uint32_t o0 = (uint32_t)ldrow * 128u + ldseg;
#pragma unroll
        for (int q = 0; q < 4; q++) {
            uint32_t off = o0 + q * 16;
            cpa16(t0 + SW(off), p + q * 16);
        }
    }

    // B chunk load: step s -> kc=s%4 (hi(y) chunk kc of tile s/4), buf=s%3
    auto issue = [&](int s) {
        int kc2 = s % NCHUNK, nb2 = s / NCHUNK;
        uint32_t t0 = base + OFF_B + (uint32_t)(s % 3) * TILE_BYTES;
        const char* p = (const char*)(Yhi + (size_t)(nb2 * BN + ldrow) * DIM + kc2 * 64) + ldseg;
        uint32_t o0 = (uint32_t)ldrow * 128u + ldseg;
#pragma unroll
        for (int q = 0; q < 4; q++) {
            uint32_t off = o0 + q * 16;
            cpa16(t0 + SW(off), p + q * 16);
        }
    };

    issue(0); CP_COMMIT();   // group0 = A tiles + B0
    issue(1); CP_COMMIT();   // group1 = B1

    // per-thread top-32 (sorted desc, [31]=min) over this thread's half-row
    float list[32];
#pragma unroll
    for (int t = 0; t < 32; t++) list[t] = -INFINITY;
    float pos = -INFINITY;
    const int myrow = tid >> 1;
    const int grow  = row0 + myrow;
    const int chalf = (tid & 1) * 32;

    float acc[2][8][4];

    for (int cs = 0; cs < NSTEP; cs++) {
        const int kc = cs % NCHUNK;
        const int nb = cs / NCHUNK;

        __syncthreads();                       // buf (cs+2)%3 free to overwrite
        if (cs + 2 < NSTEP) issue(cs + 2);
        CP_COMMIT();
        CP_WAIT2();                            // B(cs) landed (this thread)
        __syncthreads();                       // ... for all threads

        if (kc == 0) {
#pragma unroll
            for (int mi = 0; mi < 2; mi++)
#pragma unroll
                for (int nj = 0; nj < 8; nj++)
#pragma unroll
                    for (int e = 0; e < 4; e++) acc[mi][nj][e] = 0.0f;
        }

        const uint32_t aHT = base + OFF_A + kc * TILE_BYTES;
        const uint32_t aLT = base + OFF_A + (4 + kc) * TILE_BYTES;
        const uint32_t bT  = base + OFF_B + (uint32_t)(cs % 3) * TILE_BYTES;

#pragma unroll
        for (int ks = 0; ks < 4; ks++) {
            // B fragments once; feed both A-hi and A-lo terms
            uint32_t bf[8][2];
#pragma unroll
            for (int n4 = 0; n4 < 4; n4++) {
                uint32_t off = (uint32_t)(warp_n * 64 + n4 * 16 + ((lane >> 4) & 1) * 8
                             + (lane & 7)) * 128u
                             + ks * 32 + (((lane >> 3) & 1) << 4);
                uint32_t r[4];
                ldsm_x4(r, bT + SW(off));
                bf[2 * n4][0] = r[0]; bf[2 * n4][1] = r[1];
                bf[2 * n4 + 1][0] = r[2]; bf[2 * n4 + 1][1] = r[3];
            }
            uint32_t afh[2][4], afl[2][4];
#pragma unroll
            for (int mi = 0; mi < 2; mi++) {
                uint32_t off = (uint32_t)(warp_m * 32 + mi * 16 + (lane & 15)) * 128u
                             + ks * 32 + ((lane >> 4) << 4);
                ldsm_x4(afh[mi], aHT + SW(off));
                ldsm_x4(afl[mi], aLT + SW(off));
            }
#pragma unroll
            for (int mi = 0; mi < 2; mi++)
#pragma unroll
                for (int nj = 0; nj < 8; nj++)
                    mma16816(acc[mi][nj], afh[mi], bf[nj]);
#pragma unroll
            for (int mi = 0; mi < 2; mi++)
#pragma unroll
                for (int nj = 0; nj < 8; nj++)
                    mma16816(acc[mi][nj], afl[mi], bf[nj]);
        }

        if (kc == NCHUNK - 1) {
            // ------- epilogue for tile nb: two 64-col halves through stg ----
#pragma unroll
            for (int h = 0; h < 2; h++) {
                __syncthreads();               // prior scan done, stg free
                if (warp_n == h) {
#pragma unroll
                    for (int mi = 0; mi < 2; mi++)
#pragma unroll
                        for (int nj = 0; nj < 8; nj++) {
                            int r_ = warp_m * 32 + mi * 16 + (lane >> 2);
                            int c_ = nj * 8 + (lane & 3) * 2;
                            *(float2*)&stg[r_ * STG_LD + c_] =
                                make_float2(acc[mi][nj][0], acc[mi][nj][1]);
                            *(float2*)&stg[(r_ + 8) * STG_LD + c_] =
                                make_float2(acc[mi][nj][2], acc[mi][nj][3]);
                        }
                }
                __syncthreads();
                const int cb = nb * BN + h * 64 + chalf;
#pragma unroll
                for (int j = 0; j < 32; j++) {
                    float v = stg[myrow * STG_LD + chalf + j] * INV_T;
                    if (cb + j == grow) { pos = v; v = -INFINITY; }
                    if (v > list[31]) {
                        float x = v;
#pragma unroll
                        for (int t2 = 0; t2 < 32; t2++) {
                            float a_  = list[t2];
                            float hi_ = fmaxf(a_, x);
                            x         = fminf(a_, x);
                            list[t2]  = hi_;
                        }
                    }
                }
            }
        }
    }

    // ---- merge the two half-row lists of each row, emit per-row loss ------
    __syncthreads();
    float* fl = stg;                     // 256 slots x 33 floats = 8448 fits
#pragma unroll
    for (int i = 0; i < 32; i++) fl[tid * 33 + i] = list[i];
    fl[tid * 33 + 32] = pos;
    __syncthreads();
    if (!(tid & 1)) {
        const float* A_ = &fl[tid * 33];
        const float* B_ = &fl[(tid + 1) * 33];
        float pm = fmaxf(A_[32], B_[32]);            // the real diagonal logit
        float m  = fmaxf(pm, fmaxf(A_[0], B_[0]));
        float s  = expf(pm - m);
        int ia = 0, ib = 0;
        for (int it = 0; it < 32; it++) {
            float va = (ia < 32) ? A_[ia] : -INFINITY;
            float vb = (ib < 32) ? B_[ib] : -INFINITY;
            if (va >= vb) { s += expf(va - m); ia++; }
            else          { s += expf(vb - m); ib++; }
        }
        g_losses[dir * N_ROWS + grow] = m + logf(s) - pm;
    }
}

// ---------------------------------------------------------------------------
__global__ void reduce_kernel(float* __restrict__ out) {
    __shared__ double red[256];
    double s = 0.0;
    for (int i = threadIdx.x; i < 2 * N_ROWS; i += 256)
        s += (double)g_losses[i];
    red[threadIdx.x] = s;
    __syncthreads();
    for (int off = 128; off > 0; off >>= 1) {
        if (threadIdx.x < off) red[threadIdx.x] += red[threadIdx.x + off];
        __syncthreads();
    }
    if (threadIdx.x == 0)
        out[0] = (float)(red[0] / (double)(2 * N_ROWS));
}

// ---------------------------------------------------------------------------
extern "C" void kernel_launch(void* const* d_in, const int* in_sizes, int n_in,
                              void* d_out, int out_size) {
    const float* img = (const float*)d_in[0];
    const float* cur = (const float*)d_in[1];
    float* out = (float*)d_out;
    (void)in_sizes; (void)n_in; (void)out_size;

    cudaFuncSetAttribute(pass_kernel,
                         cudaFuncAttributeMaxDynamicSharedMemorySize, DYN_SMEM);

    split_kernel<<<(N_ROWS * DIM + 255) / 256, 256>>>(img, cur);
    dim3 grid(NB, 2);
    pass_kernel<<<grid, NTHREADS, DYN_SMEM>>>();
    reduce_kernel<<<1, 256>>>(out);
}

// round 8
// speedup vs baseline: 5.2561x; 1.1818x over previous
#include <cuda_runtime.h>
#include <cuda_bf16.h>
#include <math.h>
#include <stdint.h>

// ---------------------------------------------------------------------------
// HardNegativeContrastiveLoss N=8192 D=256 T=0.07 top-k=32.
// mma.sync (HMMA) single-term bf16 GEMM (logits = hi(x)·hi(y)), fused
// top-32 + logsumexp. Empirical calibration from R6/R7: each dropped
// error-split term contributes ~1e-6 rel err (row-shared lo(x) errors cancel
// between lse and pos), so plain bf16 stays ~100x under the 1e-3 gate while
// halving the HMMA instruction count (the measured binding resource).
// ---------------------------------------------------------------------------

#define N_ROWS 8192
#define DIM    256
#define INV_T  (1.0f / 0.07f)
#define BM     128
#define BN     128
#define NTHREADS 256
#define TILE_BYTES 16384        // 128 rows x 64 bf16 (128B/row), SW128
#define NCHUNK 4                // B chunks per tile (K=256)
#define NB     (N_ROWS / BN)    // 64
#define NSTEP  (NB * NCHUNK)    // 256
#define OFF_A  0
#define OFF_B  (4 * TILE_BYTES)             // 65536
#define DYN_SMEM (OFF_B + 3 * TILE_BYTES + 1024)
#define STG_LD 66               // staging row stride (floats), anti-conflict

__device__ __nv_bfloat16 g_img_hi[N_ROWS * DIM];
__device__ __nv_bfloat16 g_cur_hi[N_ROWS * DIM];
__device__ float g_losses[2 * N_ROWS];

#define SW(o) ((o) ^ (((o) >> 3) & 0x70))

__device__ __forceinline__ uint32_t smem_to_u32(const void* p) {
    uint32_t a;
    asm("{ .reg .u64 t; cvta.to.shared.u64 t, %1; cvt.u32.u64 %0, t; }"
        : "=r"(a) : "l"(p));
    return a;
}
__device__ __forceinline__ void cpa16(uint32_t dst, const void* src) {
    asm volatile("cp.async.cg.shared.global [%0], [%1], 16;"
                 :: "r"(dst), "l"(src) : "memory");
}
#define CP_COMMIT() asm volatile("cp.async.commit_group;" ::: "memory")
#define CP_WAIT2()  asm volatile("cp.async.wait_group 2;" ::: "memory")

__device__ __forceinline__ void ldsm_x4(uint32_t* r, uint32_t addr) {
    asm volatile("ldmatrix.sync.aligned.m8n8.x4.shared.b16 {%0,%1,%2,%3}, [%4];"
                 : "=r"(r[0]), "=r"(r[1]), "=r"(r[2]), "=r"(r[3]) : "r"(addr));
}
__device__ __forceinline__ void mma16816(float* c, const uint32_t* a,
                                         const uint32_t* b) {
    asm volatile(
        "mma.sync.aligned.m16n8k16.row.col.f32.bf16.bf16.f32 "
        "{%0,%1,%2,%3}, {%4,%5,%6,%7}, {%8,%9}, {%0,%1,%2,%3};"
        : "+f"(c[0]), "+f"(c[1]), "+f"(c[2]), "+f"(c[3])
        : "r"(a[0]), "r"(a[1]), "r"(a[2]), "r"(a[3]), "r"(b[0]), "r"(b[1]));
}

// ---------------------------------------------------------------------------
__global__ void split_kernel(const float* __restrict__ img,
                             const float* __restrict__ cur) {
    int i = blockIdx.x * blockDim.x + threadIdx.x;
    if (i < N_ROWS * DIM) {
        g_img_hi[i] = __float2bfloat16(img[i]);
        g_cur_hi[i] = __float2bfloat16(cur[i]);
    }
}

// ---------------------------------------------------------------------------
__global__ void __launch_bounds__(NTHREADS, 1)
pass_kernel() {
    extern __shared__ char dsm[];
    __shared__ float stg[128 * STG_LD];   // staging / merge scratch

    const uint32_t base = (smem_to_u32(dsm) + 1023u) & ~1023u;
    const int tid    = threadIdx.x;
    const int lane   = tid & 31;
    const int wid    = tid >> 5;
    const int warp_m = wid >> 1;     // 0..3 : rows warp_m*32..+31
    const int warp_n = wid & 1;      // 0..1 : cols warp_n*64..+63
    const int dir    = blockIdx.y;
    const int row0   = blockIdx.x * BM;

    const __nv_bfloat16* Xhi = dir ? g_cur_hi : g_img_hi;
    const __nv_bfloat16* Yhi = dir ? g_img_hi : g_cur_hi;

    const int ldrow = tid >> 1;            // 0..127
    const int ldseg = (tid & 1) * 64;      // byte offset within 128B row

    // ---- A resident tiles: chunks 0..3 of Xhi -----------------------------
#pragma unroll
    for (int c = 0; c < 4; c++) {
        const char* p = (const char*)(Xhi + (size_t)(row0 + ldrow) * DIM + c * 64) + ldseg;
        uint32_t t0 = base + OFF_A + c * TILE_BYTES;
        uint32_t o0 = (uint32_t)ldrow * 128u + ldseg;
#pragma unroll
        for (int q = 0; q < 4; q++) {
            uint32_t off = o0 + q * 16;
            cpa16(t0 + SW(off), p + q * 16);
        }
    }

    // B chunk load: step s -> kc=s%4 (hi(y) chunk kc of tile s/4), buf=s%3
    auto issue = [&](int s) {
        int kc2 = s % NCHUNK, nb2 = s / NCHUNK;
        uint32_t t0 = base + OFF_B + (uint32_t)(s % 3) * TILE_BYTES;
        const char* p = (const char*)(Yhi + (size_t)(nb2 * BN + ldrow) * DIM + kc2 * 64) + ldseg;
        uint32_t o0 = (uint32_t)ldrow * 128u + ldseg;
#pragma unroll
        for (int q = 0; q < 4; q++) {
            uint32_t off = o0 + q * 16;
            cpa16(t0 + SW(off), p + q * 16);
        }
    };

    issue(0); CP_COMMIT();   // group0 = A tiles + B0
    issue(1); CP_COMMIT();   // group1 = B1

    // per-thread top-32 (sorted desc, [31]=min) over this thread's half-row
    float list[32];
#pragma unroll
    for (int t = 0; t < 32; t++) list[t] = -INFINITY;
    float pos = -INFINITY;
    const int myrow = tid >> 1;
    const int grow  = row0 + myrow;
    const int chalf = (tid & 1) * 32;

    float acc[2][8][4];

    for (int cs = 0; cs < NSTEP; cs++) {
        const int kc = cs % NCHUNK;
        const int nb = cs / NCHUNK;

        __syncthreads();                       // buf (cs+2)%3 free to overwrite
        if (cs + 2 < NSTEP) issue(cs + 2);
        CP_COMMIT();
        CP_WAIT2();                            // B(cs) landed (this thread)
        __syncthreads();                       // ... for all threads

        if (kc == 0) {
#pragma unroll
            for (int mi = 0; mi < 2; mi++)
#pragma unroll
                for (int nj = 0; nj < 8; nj++)
#pragma unroll
                    for (int e = 0; e < 4; e++) acc[mi][nj][e] = 0.0f;
        }

        const uint32_t aT = base + OFF_A + kc * TILE_BYTES;
        const uint32_t bT = base + OFF_B + (uint32_t)(cs % 3) * TILE_BYTES;

#pragma unroll
        for (int ks = 0; ks < 4; ks++) {
            uint32_t bf[8][2];
#pragma unroll
            for (int n4 = 0; n4 < 4; n4++) {
                uint32_t off = (uint32_t)(warp_n * 64 + n4 * 16 + ((lane >> 4) & 1) * 8
                             + (lane & 7)) * 128u
                             + ks * 32 + (((lane >> 3) & 1) << 4);
                uint32_t r[4];
                ldsm_x4(r, bT + SW(off));
                bf[2 * n4][0] = r[0]; bf[2 * n4][1] = r[1];
                bf[2 * n4 + 1][0] = r[2]; bf[2 * n4 + 1][1] = r[3];
            }
            uint32_t af[2][4];
#pragma unroll
            for (int mi = 0; mi < 2; mi++) {
                uint32_t off = (uint32_t)(warp_m * 32 + mi * 16 + (lane & 15)) * 128u
                             + ks * 32 + ((lane >> 4) << 4);
                ldsm_x4(af[mi], aT + SW(off));
            }
#pragma unroll
            for (int mi = 0; mi < 2; mi++)
#pragma unroll
                for (int nj = 0; nj < 8; nj++)
                    mma16816(acc[mi][nj], af[mi], bf[nj]);
        }

        if (kc == NCHUNK - 1) {
            // ------- epilogue for tile nb: two 64-col halves through stg ----
#pragma unroll
            for (int h = 0; h < 2; h++) {
                __syncthreads();               // prior scan done, stg free
                if (warp_n == h) {
#pragma unroll
                    for (int mi = 0; mi < 2; mi++)
#pragma unroll
                        for (int nj = 0; nj < 8; nj++) {
                            int r_ = warp_m * 32 + mi * 16 + (lane >> 2);
                            int c_ = nj * 8 + (lane & 3) * 2;
                            *(float2*)&stg[r_ * STG_LD + c_] =
                                make_float2(acc[mi][nj][0], acc[mi][nj][1]);
                            *(float2*)&stg[(r_ + 8) * STG_LD + c_] =
                                make_float2(acc[mi][nj][2], acc[mi][nj][3]);
                        }
                }
                __syncthreads();
                const int cb = nb * BN + h * 64 + chalf;
#pragma unroll
                for (int j = 0; j < 32; j++) {
                    float v = stg[myrow * STG_LD + chalf + j] * INV_T;
                    if (cb + j == grow) { pos = v; v = -INFINITY; }
                    if (v > list[31]) {
                        float x = v;
#pragma unroll
                        for (int t2 = 0; t2 < 32; t2++) {
                            float a_  = list[t2];
                            float hi_ = fmaxf(a_, x);
                            x         = fminf(a_, x);
                            list[t2]  = hi_;
                        }
                    }
                }
            }
        }
    }

    // ---- merge the two half-row lists of each row, emit per-row loss ------
    __syncthreads();
    float* fl = stg;                     // 256 slots x 33 floats = 8448 fits
#pragma unroll
    for (int i = 0; i < 32; i++) fl[tid * 33 + i] = list[i];
    fl[tid * 33 + 32] = pos;
    __syncthreads();
    if (!(tid & 1)) {
        const float* A_ = &fl[tid * 33];
        const float* B_ = &fl[(tid + 1) * 33];
        float pm = fmaxf(A_[32], B_[32]);            // the real diagonal logit
        float m  = fmaxf(pm, fmaxf(A_[0], B_[0]));
        float s  = expf(pm - m);
        int ia = 0, ib = 0;
        for (int it = 0; it < 32; it++) {
            float va = (ia < 32) ? A_[ia] : -INFINITY;
            float vb = (ib < 32) ? B_[ib] : -INFINITY;
            if (va >= vb) { s += expf(va - m); ia++; }
            else          { s += expf(vb - m); ib++; }
        }
        g_losses[dir * N_ROWS + grow] = m + logf(s) - pm;
    }
}

// ---------------------------------------------------------------------------
__global__ void reduce_kernel(float* __restrict__ out) {
    __shared__ double red[256];
    double s = 0.0;
    for (int i = threadIdx.x; i < 2 * N_ROWS; i += 256)
        s += (double)g_losses[i];
    red[threadIdx.x] = s;
    __syncthreads();
    for (int off = 128; off > 0; off >>= 1) {
        if (threadIdx.x < off) red[threadIdx.x] += red[threadIdx.x + off];
        __syncthreads();
    }
    if (threadIdx.x == 0)
        out[0] = (float)(red[0] / (double)(2 * N_ROWS));
}

// ---------------------------------------------------------------------------
extern "C" void kernel_launch(void* const* d_in, const int* in_sizes, int n_in,
                              void* d_out, int out_size) {
    const float* img = (const float*)d_in[0];
    const float* cur = (const float*)d_in[1];
    float* out = (float*)d_out;
    (void)in_sizes; (void)n_in; (void)out_size;

    cudaFuncSetAttribute(pass_kernel,
                         cudaFuncAttributeMaxDynamicSharedMemorySize, DYN_SMEM);

    split_kernel<<<(N_ROWS * DIM + 255) / 256, 256>>>(img, cur);
    dim3 grid(NB, 2);
    pass_kernel<<<grid, NTHREADS, DYN_SMEM>>>();
    reduce_kernel<<<1, 256>>>(out);
}

// round 9
// speedup vs baseline: 6.1217x; 1.1647x over previous
#include <cuda_runtime.h>
#include <cuda_bf16.h>
#include <math.h>
#include <stdint.h>

// ---------------------------------------------------------------------------
// HardNegativeContrastiveLoss N=8192 D=256 T=0.07 top-k=32.
// bf16 mma.sync GEMM + fused top-32/logsumexp.
// R9: B/A tiles fed by cp.async.bulk (UBLKCP, baseline sm_90 PTX) from a
// pre-tiled pre-swizzled global layout; 64 fat steps (full K per step),
// double-buffered 64KB B ring + mbarrier transaction counts. Removes the
// ~300us LDGSTS issue cost and ~100us of per-step sync overhead vs R8.
// ---------------------------------------------------------------------------

#define N_ROWS 8192
#define DIM    256
#define INV_T  (1.0f / 0.07f)
#define BM     128
#define BN     128
#define NTHREADS 256
#define CHUNK  16384            // 128 rows x 64 bf16 (128B/row), SW128
#define TILE64 65536            // one full 128x256 bf16 tile (4 chunks)
#define NTILE  64
#define OFF_A  0
#define OFF_B  65536
#define DYN_SMEM (1024 + 3 * 65536)   // align slack + A + 2 B buffers
#define STG_LD 66               // staging row stride (floats), anti-conflict

__device__ unsigned char g_img_t[NTILE * TILE64];   // tiled+swizzled bf16
__device__ unsigned char g_cur_t[NTILE * TILE64];
__device__ float g_losses[2 * N_ROWS];

#define SW(o) ((o) ^ (((o) >> 3) & 0x70))

__device__ __forceinline__ uint32_t smem_to_u32(const void* p) {
    uint32_t a;
    asm("{ .reg .u64 t; cvta.to.shared.u64 t, %1; cvt.u32.u64 %0, t; }"
        : "=r"(a) : "l"(p));
    return a;
}
__device__ __forceinline__ void bulk_cp(uint32_t dst, const void* src,
                                        uint32_t bytes, uint32_t mbar) {
    asm volatile(
        "cp.async.bulk.shared::cluster.global.mbarrier::complete_tx::bytes "
        "[%0], [%1], %2, [%3];"
        :: "r"(dst), "l"(src), "r"(bytes), "r"(mbar) : "memory");
}
#define MBARRIER_INIT(mbar, count) \
    asm volatile("mbarrier.init.shared.b64 [%0], %1;" \
        :: "r"((uint32_t)(mbar)), "r"((uint32_t)(count)) : "memory")
#define MBARRIER_EXPECT_TX(mbar, bytes) \
    asm volatile("mbarrier.arrive.expect_tx.shared.b64 _, [%0], %1;" \
        :: "r"((uint32_t)(mbar)), "r"((uint32_t)(bytes)) : "memory")
#define MBARRIER_WAIT_PARITY(mbar, parity) do { \
    uint32_t _m = (uint32_t)(mbar); uint32_t _p = (uint32_t)(parity); uint32_t _d; \
    asm volatile("{\n\t.reg .pred p;\n\t" \
        "mbarrier.try_wait.parity.acquire.cta.shared::cta.b64 p, [%1], %2;\n\t" \
        "selp.b32 %0, 1, 0, p;\n\t}" : "=r"(_d) : "r"(_m), "r"(_p) : "memory"); \
    if (!_d) { \
        asm volatile("{\n\t.reg .pred P1;\n\t" \
            "WL_%=:\n\t" \
            "mbarrier.try_wait.parity.acquire.cta.shared::cta.b64 P1, [%0], %1, 0x989680;\n\t" \
            "@P1 bra.uni WD_%=;\n\t" \
            "bra.uni WL_%=;\n\t" \
            "WD_%=:\n\t}" :: "r"(_m), "r"(_p) : "memory"); \
    } \
} while (0)

__device__ __forceinline__ void ldsm_x4(uint32_t* r, uint32_t addr) {
    asm volatile("ldmatrix.sync.aligned.m8n8.x4.shared.b16 {%0,%1,%2,%3}, [%4];"
                 : "=r"(r[0]), "=r"(r[1]), "=r"(r[2]), "=r"(r[3]) : "r"(addr));
}
__device__ __forceinline__ void mma16816(float* c, const uint32_t* a,
                                         const uint32_t* b) {
    asm volatile(
        "mma.sync.aligned.m16n8k16.row.col.f32.bf16.bf16.f32 "
        "{%0,%1,%2,%3}, {%4,%5,%6,%7}, {%8,%9}, {%0,%1,%2,%3};"
        : "+f"(c[0]), "+f"(c[1]), "+f"(c[2]), "+f"(c[3])
        : "r"(a[0]), "r"(a[1]), "r"(a[2]), "r"(a[3]), "r"(b[0]), "r"(b[1]));
}

// ---------------------------------------------------------------------------
// fp32 -> bf16, written into tiled + SW128-pre-swizzled layout:
// element (n,d) -> tile n/128, chunk d/64, offset SW((n%128)*128 + (d%64)*2)
__global__ void split_kernel(const float* __restrict__ img,
                             const float* __restrict__ cur) {
    int i = blockIdx.x * blockDim.x + threadIdx.x;
    if (i < N_ROWS * DIM) {
        int n = i >> 8, d = i & 255;
        uint32_t off = (uint32_t)(n & 127) * 128u + (uint32_t)(d & 63) * 2u;
        size_t addr = (size_t)(n >> 7) * TILE64 + (size_t)(d >> 6) * CHUNK
                    + SW(off);
        *(__nv_bfloat16*)(g_img_t + addr) = __float2bfloat16(img[i]);
        *(__nv_bfloat16*)(g_cur_t + addr) = __float2bfloat16(cur[i]);
    }
}

// ---------------------------------------------------------------------------
__global__ void __launch_bounds__(NTHREADS, 1)
pass_kernel() {
    extern __shared__ char dsm[];
    __shared__ float stg[128 * STG_LD];      // staging / merge scratch
    __shared__ __align__(8) unsigned long long mbars[2];

    const uint32_t base = (smem_to_u32(dsm) + 1023u) & ~1023u;
    const uint32_t mb0 = smem_to_u32(&mbars[0]);
    const uint32_t mb1 = smem_to_u32(&mbars[1]);
    const int tid    = threadIdx.x;
    const int lane   = tid & 31;
    const int wid    = tid >> 5;
    const int warp_m = wid >> 1;     // 0..3 : rows warp_m*32..+31
    const int warp_n = wid & 1;      // 0..1 : cols warp_n*64..+63
    const int dir    = blockIdx.y;
    const int row0   = blockIdx.x * BM;

    const unsigned char* Xt = dir ? g_cur_t : g_img_t;
    const unsigned char* Yt = dir ? g_img_t : g_cur_t;

    if (tid == 0) { MBARRIER_INIT(mb0, 1); MBARRIER_INIT(mb1, 1); }
    __syncthreads();

    if (tid == 0) {
        // A (64KB) + B tile 0 (64KB) on mb0; B tile 1 on mb1.
        MBARRIER_EXPECT_TX(mb0, TILE64 * 2);
        bulk_cp(base + OFF_A, Xt + (size_t)blockIdx.x * TILE64, TILE64, mb0);
        bulk_cp(base + OFF_B, Yt, TILE64, mb0);
        MBARRIER_EXPECT_TX(mb1, TILE64);
        bulk_cp(base + OFF_B + TILE64, Yt + TILE64, TILE64, mb1);
    }

    // per-thread top-32 (sorted desc, [31]=min) over this thread's half-row
    float list[32];
#pragma unroll
    for (int t = 0; t < 32; t++) list[t] = -INFINITY;
    float pos = -INFINITY;
    const int myrow = tid >> 1;
    const int grow  = row0 + myrow;
    const int chalf = (tid & 1) * 32;

    float acc[2][8][4];

    for (int t = 0; t < NTILE; t++) {
        MBARRIER_WAIT_PARITY(t & 1 ? mb1 : mb0, (t >> 1) & 1);

#pragma unroll
        for (int mi = 0; mi < 2; mi++)
#pragma unroll
            for (int nj = 0; nj < 8; nj++)
#pragma unroll
                for (int e = 0; e < 4; e++) acc[mi][nj][e] = 0.0f;

        const uint32_t bTile = base + OFF_B + (uint32_t)(t & 1) * TILE64;

#pragma unroll
        for (int kc = 0; kc < 4; kc++) {
            const uint32_t aT = base + OFF_A + kc * CHUNK;
            const uint32_t bT = bTile + kc * CHUNK;
#pragma unroll
            for (int ks = 0; ks < 4; ks++) {
                uint32_t bf[8][2];
#pragma unroll
                for (int n4 = 0; n4 < 4; n4++) {
                    uint32_t off = (uint32_t)(warp_n * 64 + n4 * 16 + ((lane >> 4) & 1) * 8
                                 + (lane & 7)) * 128u
                                 + ks * 32 + (((lane >> 3) & 1) << 4);
                    uint32_t r[4];
                    ldsm_x4(r, bT + SW(off));
                    bf[2 * n4][0] = r[0]; bf[2 * n4][1] = r[1];
                    bf[2 * n4 + 1][0] = r[2]; bf[2 * n4 + 1][1] = r[3];
                }
                uint32_t af[2][4];
#pragma unroll
                for (int mi = 0; mi < 2; mi++) {
                    uint32_t off = (uint32_t)(warp_m * 32 + mi * 16 + (lane & 15)) * 128u
                                 + ks * 32 + ((lane >> 4) << 4);
                    ldsm_x4(af[mi], aT + SW(off));
                }
#pragma unroll
                for (int mi = 0; mi < 2; mi++)
#pragma unroll
                    for (int nj = 0; nj < 8; nj++)
                        mma16816(acc[mi][nj], af[mi], bf[nj]);
            }
        }

        // ------- epilogue for tile t: two 64-col halves through stg --------
#pragma unroll
        for (int h = 0; h < 2; h++) {
            __syncthreads();               // h=0: all MMA done -> buffer dead
            if (h == 0 && tid == 0 && t + 2 < NTILE) {
                // refill this step's buffer for step t+2 (reads all done)
                const uint32_t mbr = (t & 1) ? mb1 : mb0;
                MBARRIER_EXPECT_TX(mbr, TILE64);
                bulk_cp(bTile, Yt + (size_t)(t + 2) * TILE64, TILE64, mbr);
            }
            if (warp_n == h) {
#pragma unroll
                for (int mi = 0; mi < 2; mi++)
#pragma unroll
                    for (int nj = 0; nj < 8; nj++) {
                        int r_ = warp_m * 32 + mi * 16 + (lane >> 2);
                        int c_ = nj * 8 + (lane & 3) * 2;
                        *(float2*)&stg[r_ * STG_LD + c_] =
                            make_float2(acc[mi][nj][0], acc[mi][nj][1]);
                        *(float2*)&stg[(r_ + 8) * STG_LD + c_] =
                            make_float2(acc[mi][nj][2], acc[mi][nj][3]);
                    }
            }
            __syncthreads();
            const int cb = t * BN + h * 64 + chalf;
#pragma unroll
            for (int j = 0; j < 32; j++) {
                float v = stg[myrow * STG_LD + chalf + j] * INV_T;
                if (cb + j == grow) { pos = v; v = -INFINITY; }
                if (v > list[31]) {
                    float x = v;
#pragma unroll
                    for (int t2 = 0; t2 < 32; t2++) {
                        float a_  = list[t2];
                        float hi_ = fmaxf(a_, x);
                        x         = fminf(a_, x);
                        list[t2]  = hi_;
                    }
                }
            }
        }
    }

    // ---- merge the two half-row lists of each row, emit per-row loss ------
    __syncthreads();
    float* fl = stg;                     // 256 slots x 33 floats = 8448 fits
#pragma unroll
    for (int i = 0; i < 32; i++) fl[tid * 33 + i] = list[i];
    fl[tid * 33 + 32] = pos;
    __syncthreads();
    if (!(tid & 1)) {
        const float* A_ = &fl[tid * 33];
        const float* B_ = &fl[(tid + 1) * 33];
        float pm = fmaxf(A_[32], B_[32]);            // the real diagonal logit
        float m  = fmaxf(pm, fmaxf(A_[0], B_[0]));
        float s  = expf(pm - m);
        int ia = 0, ib = 0;
        for (int it = 0; it < 32; it++) {
            float va = (ia < 32) ? A_[ia] : -INFINITY;
            float vb = (ib < 32) ? B_[ib] : -INFINITY;
            if (va >= vb) { s += expf(va - m); ia++; }
            else          { s += expf(vb - m); ib++; }
        }
        g_losses[dir * N_ROWS + grow] = m + logf(s) - pm;
    }
}

// ---------------------------------------------------------------------------
__global__ void reduce_kernel(float* __restrict__ out) {
    __shared__ double red[256];
    double s = 0.0;
    for (int i = threadIdx.x; i < 2 * N_ROWS; i += 256)
        s += (double)g_losses[i];
    red[threadIdx.x] = s;
    __syncthreads();
    for (int off = 128; off > 0; off >>= 1) {
        if (threadIdx.x < off) red[threadIdx.x] += red[threadIdx.x + off];
        __syncthreads();
    }
    if (threadIdx.x == 0)
        out[0] = (float)(red[0] / (double)(2 * N_ROWS));
}

// ---------------------------------------------------------------------------
extern "C" void kernel_launch(void* const* d_in, const int* in_sizes, int n_in,
                              void* d_out, int out_size) {
    const float* img = (const float*)d_in[0];
    const float* cur = (const float*)d_in[1];
    float* out = (float*)d_out;
    (void)in_sizes; (void)n_in; (void)out_size;

    cudaFuncSetAttribute(pass_kernel,
                         cudaFuncAttributeMaxDynamicSharedMemorySize, DYN_SMEM);

    split_kernel<<<(N_ROWS * DIM + 255) / 256, 256>>>(img, cur);
    dim3 grid(NTILE, 2);
    pass_kernel<<<grid, NTHREADS, DYN_SMEM>>>();
    reduce_kernel<<<1, 256>>>(out);
}